// round 1
// baseline (speedup 1.0000x reference)
#include <cuda_runtime.h>
#include <cstdint>
#include <math_constants.h>

#define NB 32
#define NL 512
#define ND 512
#define NH 8
#define NDH 64
#define MTOT (NB*NL)            // 16384 rows

#define SQ_STRIDE 68            // 64 cols + 4 pad (bank-conflict-free frag loads)
#define SW_STRIDE 132           // 128 cols + 4 pad
#define ATTN_SMEM ((3*128*SQ_STRIDE + 128*SW_STRIDE + 128) * (int)sizeof(float))

// ---------------- scratch (static device memory; no allocs allowed) ----------
__device__ float g_Q[(size_t)MTOT * ND];
__device__ float g_K[(size_t)MTOT * ND];
__device__ float g_V[(size_t)MTOT * ND];
__device__ float g_qm[MTOT];
__device__ float g_km[MTOT];

// ---------------- helpers ----------------------------------------------------
__device__ __forceinline__ uint32_t tf32u(float x) {
    uint32_t u;
    asm("cvt.rna.tf32.f32 %0, %1;" : "=r"(u) : "f"(x));
    return u;
}
__device__ __forceinline__ float tf32r(float x) {
    return __uint_as_float(tf32u(x));
}
// D = A(16x8 row) * B(8x8 col) + D, tf32 inputs, f32 accum
__device__ __forceinline__ void mma8(float c[4], const uint32_t a[4], uint32_t b0, uint32_t b1) {
    asm volatile(
        "mma.sync.aligned.m16n8k8.row.col.f32.tf32.tf32.f32 "
        "{%0,%1,%2,%3},{%4,%5,%6,%7},{%8,%9},{%0,%1,%2,%3};\n"
        : "+f"(c[0]), "+f"(c[1]), "+f"(c[2]), "+f"(c[3])
        : "r"(a[0]), "r"(a[1]), "r"(a[2]), "r"(a[3]), "r"(b0), "r"(b1));
}

// ---------------- kernel 1: sign masks ---------------------------------------
__global__ void mask_kernel(const float* __restrict__ q, const float* __restrict__ k) {
    int warp = threadIdx.x >> 5, lane = threadIdx.x & 31;
    int row = blockIdx.x * 4 + warp;
    const float4* q4 = reinterpret_cast<const float4*>(q + (size_t)row * ND);
    const float4* k4 = reinterpret_cast<const float4*>(k + (size_t)row * ND);
    float sq = 0.f, sk = 0.f;
#pragma unroll
    for (int i = 0; i < 4; i++) {
        float4 a = q4[lane + 32 * i];
        sq += fabsf(a.x) + fabsf(a.y) + fabsf(a.z) + fabsf(a.w);
        float4 b = k4[lane + 32 * i];
        sk += fabsf(b.x) + fabsf(b.y) + fabsf(b.z) + fabsf(b.w);
    }
#pragma unroll
    for (int o = 16; o; o >>= 1) {
        sq += __shfl_xor_sync(0xffffffffu, sq, o);
        sk += __shfl_xor_sync(0xffffffffu, sk, o);
    }
    if (lane == 0) {
        g_qm[row] = sq > 0.f ? 1.f : 0.f;
        g_km[row] = sk > 0.f ? 1.f : 0.f;
    }
}

// ---------------- kernel 2: projection GEMM  C = X @ W^T + b ------------------
// X [16384,512] row-major, W [512,512] row-major (both K-contiguous → NT GEMM)
__global__ __launch_bounds__(256) void proj_kernel(
    const float* __restrict__ X, const float* __restrict__ Wt,
    const float* __restrict__ bias, int which) {
    float* out = (which == 0) ? g_Q : (which == 1) ? g_K : g_V;
    __shared__ float As[128][36];
    __shared__ float Bs[128][36];
    const int tid = threadIdx.x, wid = tid >> 5, lane = tid & 31;
    const int g = lane >> 2, tg = lane & 3;
    const int wm = (wid >> 2) * 64, wn = (wid & 3) * 32;  // 2x4 warps, 64x32 tiles
    const int m0 = blockIdx.y * 128, n0 = blockIdx.x * 128;

    float acc[4][4][4];
#pragma unroll
    for (int mi = 0; mi < 4; mi++)
#pragma unroll
        for (int ni = 0; ni < 4; ni++)
#pragma unroll
            for (int e = 0; e < 4; e++) acc[mi][ni][e] = 0.f;

    for (int kb = 0; kb < ND; kb += 32) {
#pragma unroll
        for (int j = 0; j < 4; j++) {
            int fi = tid + 256 * j, r = fi >> 3, c4 = fi & 7;
            float4 va = *reinterpret_cast<const float4*>(X + (size_t)(m0 + r) * ND + kb + c4 * 4);
            As[r][c4 * 4 + 0] = tf32r(va.x); As[r][c4 * 4 + 1] = tf32r(va.y);
            As[r][c4 * 4 + 2] = tf32r(va.z); As[r][c4 * 4 + 3] = tf32r(va.w);
            float4 vb = *reinterpret_cast<const float4*>(Wt + (size_t)(n0 + r) * ND + kb + c4 * 4);
            Bs[r][c4 * 4 + 0] = tf32r(vb.x); Bs[r][c4 * 4 + 1] = tf32r(vb.y);
            Bs[r][c4 * 4 + 2] = tf32r(vb.z); Bs[r][c4 * 4 + 3] = tf32r(vb.w);
        }
        __syncthreads();
#pragma unroll
        for (int ks = 0; ks < 4; ks++) {
            const int k0 = ks * 8;
            uint32_t af[4][4], bf[4][2];
#pragma unroll
            for (int mi = 0; mi < 4; mi++) {
                const int rb = wm + mi * 16;
                af[mi][0] = __float_as_uint(As[rb + g][k0 + tg]);
                af[mi][1] = __float_as_uint(As[rb + g + 8][k0 + tg]);
                af[mi][2] = __float_as_uint(As[rb + g][k0 + tg + 4]);
                af[mi][3] = __float_as_uint(As[rb + g + 8][k0 + tg + 4]);
            }
#pragma unroll
            for (int ni = 0; ni < 4; ni++) {
                bf[ni][0] = __float_as_uint(Bs[wn + ni * 8 + g][k0 + tg]);
                bf[ni][1] = __float_as_uint(Bs[wn + ni * 8 + g][k0 + tg + 4]);
            }
#pragma unroll
            for (int mi = 0; mi < 4; mi++)
#pragma unroll
                for (int ni = 0; ni < 4; ni++)
                    mma8(acc[mi][ni], af[mi], bf[ni][0], bf[ni][1]);
        }
        __syncthreads();
    }
#pragma unroll
    for (int mi = 0; mi < 4; mi++) {
#pragma unroll
        for (int ni = 0; ni < 4; ni++) {
            int row = m0 + wm + mi * 16 + g;
            int col = n0 + wn + ni * 8 + 2 * tg;
            float b0 = bias[col], b1 = bias[col + 1];
            *reinterpret_cast<float2*>(out + (size_t)row * ND + col) =
                make_float2(acc[mi][ni][0] + b0, acc[mi][ni][1] + b1);
            *reinterpret_cast<float2*>(out + (size_t)(row + 8) * ND + col) =
                make_float2(acc[mi][ni][2] + b0, acc[mi][ni][3] + b1);
        }
    }
}

// ---------------- kernel 3: attention ----------------------------------------
__device__ __forceinline__ void compute_S(const float* sQ, const float* sK,
                                          int wid, int g, int tg, float (&acc)[16][4]) {
#pragma unroll
    for (int ni = 0; ni < 16; ni++)
#pragma unroll
        for (int e = 0; e < 4; e++) acc[ni][e] = 0.f;
#pragma unroll
    for (int ks = 0; ks < 8; ks++) {
        const int k0 = ks * 8;
        const float* qrow = sQ + (size_t)(wid * 16 + g) * SQ_STRIDE + k0;
        uint32_t af[4];
        af[0] = __float_as_uint(qrow[tg]);
        af[1] = __float_as_uint(qrow[8 * SQ_STRIDE + tg]);
        af[2] = __float_as_uint(qrow[tg + 4]);
        af[3] = __float_as_uint(qrow[8 * SQ_STRIDE + tg + 4]);
#pragma unroll
        for (int ni = 0; ni < 16; ni++) {
            const float* krow = sK + (size_t)(ni * 8 + g) * SQ_STRIDE + k0;
            mma8(acc[ni], af, __float_as_uint(krow[tg]), __float_as_uint(krow[tg + 4]));
        }
    }
}

__device__ __forceinline__ void apply_mask(float (&acc)[16][4], const float* sKM,
                                           int kt, int causal, int rowg0, int rowg1, int tg) {
#pragma unroll
    for (int ni = 0; ni < 16; ni++)
#pragma unroll
        for (int e = 0; e < 4; e++) {
            int r = e >> 1, c = e & 1;
            int col = ni * 8 + 2 * tg + c;
            int colg = kt * 128 + col;
            float s = acc[ni][e] * 0.125f;  // 1/sqrt(64)
            if (sKM[col] == 0.f) s = -CUDART_INF_F;
            if (causal && colg > (r ? rowg1 : rowg0)) s = -CUDART_INF_F;
            acc[ni][e] = s;
        }
}

__global__ __launch_bounds__(256, 1) void attn_kernel(
    const int* __restrict__ causality, float* __restrict__ outp, float* __restrict__ attnp) {
    extern __shared__ float sh[];
    float* sQ = sh;
    float* sK = sQ + 128 * SQ_STRIDE;
    float* sV = sK + 128 * SQ_STRIDE;
    float* sW = sV + 128 * SQ_STRIDE;
    float* sKM = sW + 128 * SW_STRIDE;

    const int qt = blockIdx.x, h = blockIdx.y, b = blockIdx.z;
    const int tid = threadIdx.x, wid = tid >> 5, lane = tid & 31;
    const int g = lane >> 2, tg = lane & 3;
    const int causal = *causality;
    const int q0 = qt * 128;

    // stage Q tile (pre-rounded to tf32)
#pragma unroll
    for (int j = 0; j < 8; j++) {
        int fi = tid + 256 * j, r = fi >> 4, c4 = fi & 15;
        float4 v = *reinterpret_cast<const float4*>(
            g_Q + (size_t)(b * NL + q0 + r) * ND + h * NDH + c4 * 4);
        float4 w;
        w.x = tf32r(v.x); w.y = tf32r(v.y); w.z = tf32r(v.z); w.w = tf32r(v.w);
        *reinterpret_cast<float4*>(sQ + r * SQ_STRIDE + c4 * 4) = w;
    }

    const int rowl0 = wid * 16 + g, rowl1 = rowl0 + 8;
    const int rowg0 = q0 + rowl0, rowg1 = q0 + rowl1;
    const float qm0 = g_qm[b * NL + rowg0];
    const float qm1 = g_qm[b * NL + rowg1];

    float mrun[2] = {-CUDART_INF_F, -CUDART_INF_F};
    float lrun[2] = {0.f, 0.f};
    const int ktmax = causal ? qt : 3;
    float acc[16][4];

    // ---- PASS A: softmax statistics ----
    for (int kt = 0; kt <= ktmax; kt++) {
#pragma unroll
        for (int j = 0; j < 8; j++) {
            int fi = tid + 256 * j, r = fi >> 4, c4 = fi & 15;
            float4 v = *reinterpret_cast<const float4*>(
                g_K + (size_t)(b * NL + kt * 128 + r) * ND + h * NDH + c4 * 4);
            float4 w;
            w.x = tf32r(v.x); w.y = tf32r(v.y); w.z = tf32r(v.z); w.w = tf32r(v.w);
            *reinterpret_cast<float4*>(sK + r * SQ_STRIDE + c4 * 4) = w;
        }
        if (tid < 128) sKM[tid] = g_km[b * NL + kt * 128 + tid];
        __syncthreads();

        compute_S(sQ, sK, wid, g, tg, acc);
        apply_mask(acc, sKM, kt, causal, rowg0, rowg1, tg);

#pragma unroll
        for (int r = 0; r < 2; r++) {
            float mx = -CUDART_INF_F;
#pragma unroll
            for (int ni = 0; ni < 16; ni++) {
                mx = fmaxf(mx, acc[ni][2 * r]);
                mx = fmaxf(mx, acc[ni][2 * r + 1]);
            }
            mx = fmaxf(mx, __shfl_xor_sync(0xffffffffu, mx, 1));
            mx = fmaxf(mx, __shfl_xor_sync(0xffffffffu, mx, 2));
            float mn = fmaxf(mrun[r], mx);
            if (mn != -CUDART_INF_F) {
                float ps = 0.f;
#pragma unroll
                for (int ni = 0; ni < 16; ni++) {
                    ps += __expf(acc[ni][2 * r] - mn);
                    ps += __expf(acc[ni][2 * r + 1] - mn);
                }
                ps += __shfl_xor_sync(0xffffffffu, ps, 1);
                ps += __shfl_xor_sync(0xffffffffu, ps, 2);
                lrun[r] = lrun[r] * __expf(mrun[r] - mn) + ps;
                mrun[r] = mn;
            }
        }
        __syncthreads();
    }

    float muse[2], invl[2];
    muse[0] = lrun[0] > 0.f ? mrun[0] : 0.f;
    invl[0] = lrun[0] > 0.f ? qm0 / lrun[0] : 0.f;
    muse[1] = lrun[1] > 0.f ? mrun[1] : 0.f;
    invl[1] = lrun[1] > 0.f ? qm1 / lrun[1] : 0.f;

    float oacc[8][4];
#pragma unroll
    for (int ni = 0; ni < 8; ni++)
#pragma unroll
        for (int e = 0; e < 4; e++) oacc[ni][e] = 0.f;

    // ---- PASS B: weights out + O accumulation ----
    for (int kt = 0; kt < 4; kt++) {
        if (causal && kt > qt) {
            if (attnp) {
                float4 z = make_float4(0.f, 0.f, 0.f, 0.f);
#pragma unroll
                for (int j = 0; j < 16; j++) {
                    int row = wid * 16 + j;
                    *reinterpret_cast<float4*>(
                        attnp + ((size_t)(b * NH + h) * NL + q0 + row) * NL + kt * 128 + lane * 4) = z;
                }
            }
            continue;
        }
#pragma unroll
        for (int j = 0; j < 8; j++) {
            int fi = tid + 256 * j, r = fi >> 4, c4 = fi & 15;
            float4 v = *reinterpret_cast<const float4*>(
                g_K + (size_t)(b * NL + kt * 128 + r) * ND + h * NDH + c4 * 4);
            float4 w;
            w.x = tf32r(v.x); w.y = tf32r(v.y); w.z = tf32r(v.z); w.w = tf32r(v.w);
            *reinterpret_cast<float4*>(sK + r * SQ_STRIDE + c4 * 4) = w;
            float4 vv = *reinterpret_cast<const float4*>(
                g_V + (size_t)(b * NL + kt * 128 + r) * ND + h * NDH + c4 * 4);
            float4 wv;
            wv.x = tf32r(vv.x); wv.y = tf32r(vv.y); wv.z = tf32r(vv.z); wv.w = tf32r(vv.w);
            *reinterpret_cast<float4*>(sV + r * SQ_STRIDE + c4 * 4) = wv;
        }
        if (tid < 128) sKM[tid] = g_km[b * NL + kt * 128 + tid];
        __syncthreads();

        compute_S(sQ, sK, wid, g, tg, acc);
        apply_mask(acc, sKM, kt, causal, rowg0, rowg1, tg);

        // normalized weights into sW (fp32; tf32-rounded only at the O-mma load)
#pragma unroll
        for (int ni = 0; ni < 16; ni++)
#pragma unroll
            for (int e = 0; e < 4; e++) {
                int r = e >> 1, c = e & 1;
                float wv = __expf(acc[ni][e] - muse[r]) * invl[r];
                int rowl = r ? rowl1 : rowl0;
                sW[(size_t)rowl * SW_STRIDE + ni * 8 + 2 * tg + c] = wv;
            }
        __syncwarp();

        if (attnp) {
#pragma unroll
            for (int j = 0; j < 16; j++) {
                int row = wid * 16 + j;
                float4 v = *reinterpret_cast<float4*>(sW + (size_t)row * SW_STRIDE + lane * 4);
                *reinterpret_cast<float4*>(
                    attnp + ((size_t)(b * NH + h) * NL + q0 + row) * NL + kt * 128 + lane * 4) = v;
            }
        }

        // O += W * V
#pragma unroll
        for (int ks = 0; ks < 16; ks++) {
            const int k0 = ks * 8;
            const float* wrow = sW + (size_t)(wid * 16 + g) * SW_STRIDE + k0;
            uint32_t af[4];
            af[0] = tf32u(wrow[tg]);
            af[1] = tf32u(wrow[8 * SW_STRIDE + tg]);
            af[2] = tf32u(wrow[tg + 4]);
            af[3] = tf32u(wrow[8 * SW_STRIDE + tg + 4]);
#pragma unroll
            for (int ni = 0; ni < 8; ni++) {
                uint32_t b0 = __float_as_uint(sV[(size_t)(k0 + tg) * SQ_STRIDE + ni * 8 + g]);
                uint32_t b1 = __float_as_uint(sV[(size_t)(k0 + tg + 4) * SQ_STRIDE + ni * 8 + g]);
                mma8(oacc[ni], af, b0, b1);
            }
        }
        __syncthreads();
    }

    // epilogue: out[b][q][h*64 + d]
#pragma unroll
    for (int ni = 0; ni < 8; ni++) {
        int col = h * NDH + ni * 8 + 2 * tg;
        *reinterpret_cast<float2*>(outp + ((size_t)b * NL + rowg0) * ND + col) =
            make_float2(oacc[ni][0], oacc[ni][1]);
        *reinterpret_cast<float2*>(outp + ((size_t)b * NL + rowg1) * ND + col) =
            make_float2(oacc[ni][2], oacc[ni][3]);
    }
}

// ---------------- launcher ----------------------------------------------------
extern "C" void kernel_launch(void* const* d_in, const int* in_sizes, int n_in,
                              void* d_out, int out_size) {
    (void)in_sizes; (void)n_in;
    const float* queries = (const float*)d_in[0];
    const float* keys    = (const float*)d_in[1];
    const float* Wq = (const float*)d_in[2];
    const float* bq = (const float*)d_in[3];
    const float* Wk = (const float*)d_in[4];
    const float* bk = (const float*)d_in[5];
    const float* Wv = (const float*)d_in[6];
    const float* bv = (const float*)d_in[7];
    const int* caus = (const int*)d_in[8];

    float* outp = (float*)d_out;
    const size_t o_elems = (size_t)NB * NL * ND;
    const size_t a_elems = (size_t)NB * NH * NL * NL;
    float* attnp = ((size_t)out_size >= o_elems + a_elems) ? (outp + o_elems) : nullptr;

    cudaFuncSetAttribute(attn_kernel, cudaFuncAttributeMaxDynamicSharedMemorySize, ATTN_SMEM);

    mask_kernel<<<MTOT / 4, 128>>>(queries, keys);
    proj_kernel<<<dim3(4, 128), 256>>>(queries, Wq, bq, 0);
    proj_kernel<<<dim3(4, 128), 256>>>(keys, Wk, bk, 1);
    proj_kernel<<<dim3(4, 128), 256>>>(keys, Wv, bv, 2);
    attn_kernel<<<dim3(4, NH, NB), 256, ATTN_SMEM>>>(caus, outp, attnp);
}

// round 2
// speedup vs baseline: 1.0063x; 1.0063x over previous
#include <cuda_runtime.h>
#include <cstdint>
#include <math_constants.h>

#define NB 32
#define NL 512
#define ND 512
#define NH 8
#define NDH 64
#define MTOT (NB*NL)

// ---------------- scratch (static device memory; no allocs allowed) ----------
__device__ float g_Q[(size_t)MTOT * ND];
__device__ float g_K[(size_t)MTOT * ND];
__device__ float g_V[(size_t)MTOT * ND];
__device__ float g_qm[MTOT];
__device__ float g_km[MTOT];

// ---------------- helpers ----------------------------------------------------
__device__ __forceinline__ uint32_t tf32u(float x) {
    uint32_t u;
    asm("cvt.rna.tf32.f32 %0, %1;" : "=r"(u) : "f"(x));
    return u;
}
__device__ __forceinline__ float tf32r(float x) {
    return __uint_as_float(tf32u(x));
}
__device__ __forceinline__ float ex2(float x) {
    float y;
    asm("ex2.approx.ftz.f32 %0, %1;" : "=f"(y) : "f"(x));
    return y;
}
// D = A(16x8 row) * B(8x8 col) + D, tf32 inputs, f32 accum
__device__ __forceinline__ void mma8(float c[4], const uint32_t a[4], uint32_t b0, uint32_t b1) {
    asm volatile(
        "mma.sync.aligned.m16n8k8.row.col.f32.tf32.tf32.f32 "
        "{%0,%1,%2,%3},{%4,%5,%6,%7},{%8,%9},{%0,%1,%2,%3};\n"
        : "+f"(c[0]), "+f"(c[1]), "+f"(c[2]), "+f"(c[3])
        : "r"(a[0]), "r"(a[1]), "r"(a[2]), "r"(a[3]), "r"(b0), "r"(b1));
}

#define CSCALE 0.18033688011112042f   /* (1/8) * log2(e) */

// ---------------- kernel 1: sign masks ---------------------------------------
__global__ void mask_kernel(const float* __restrict__ q, const float* __restrict__ k) {
    int warp = threadIdx.x >> 5, lane = threadIdx.x & 31;
    int row = blockIdx.x * 4 + warp;
    const float4* q4 = reinterpret_cast<const float4*>(q + (size_t)row * ND);
    const float4* k4 = reinterpret_cast<const float4*>(k + (size_t)row * ND);
    float sq = 0.f, sk = 0.f;
#pragma unroll
    for (int i = 0; i < 4; i++) {
        float4 a = q4[lane + 32 * i];
        sq += fabsf(a.x) + fabsf(a.y) + fabsf(a.z) + fabsf(a.w);
        float4 b = k4[lane + 32 * i];
        sk += fabsf(b.x) + fabsf(b.y) + fabsf(b.z) + fabsf(b.w);
    }
#pragma unroll
    for (int o = 16; o; o >>= 1) {
        sq += __shfl_xor_sync(0xffffffffu, sq, o);
        sk += __shfl_xor_sync(0xffffffffu, sk, o);
    }
    if (lane == 0) {
        g_qm[row] = sq > 0.f ? 1.f : 0.f;
        g_km[row] = sk > 0.f ? 1.f : 0.f;
    }
}

// ---------------- kernel 2: fused projection GEMMs  C = X @ W^T + b ----------
// grid.z selects (Q from queries, K/V from keys). CTA tile 128x128, k-step 32,
// double-buffered, fragment-major smem with tg^k8 swizzle.
__global__ __launch_bounds__(512, 1) void proj_kernel(
    const float* __restrict__ queries, const float* __restrict__ keys,
    const float* __restrict__ Wq, const float* __restrict__ bq,
    const float* __restrict__ Wk, const float* __restrict__ bk,
    const float* __restrict__ Wv, const float* __restrict__ bv) {
    const int which = blockIdx.z;
    const float* X    = (which == 0) ? queries : keys;
    const float* Wt   = (which == 0) ? Wq : (which == 1) ? Wk : Wv;
    const float* bias = (which == 0) ? bq : (which == 1) ? bk : bv;
    float* out        = (which == 0) ? g_Q : (which == 1) ? g_K : g_V;

    __shared__ float sA[2][4096];   // [mblk8][k8_4][g8][slot4][v4]
    __shared__ float sB[2][4096];   // [nblk16][k8_4][g8][slot4][khi2]

    const int tid = threadIdx.x, wid = tid >> 5, lane = tid & 31;
    const int g = lane >> 2, tg = lane & 3;
    const int wm2 = (wid >> 2) * 2;   // warp m-block base (2 blocks of 16 = 32 rows)
    const int wn4 = (wid & 3) * 4;    // warp n-block base (4 blocks of 8 = 32 cols)
    const int m0 = blockIdx.y * 128, n0 = blockIdx.x * 128;

    const int rr  = tid >> 3;         // staging row base 0..63
    const int c4  = tid & 7;          // which float4 in the 32-wide k slab
    const int k8s = c4 >> 1, khis = c4 & 1;

    float acc[2][4][4];
#pragma unroll
    for (int mi = 0; mi < 2; mi++)
#pragma unroll
        for (int ni = 0; ni < 4; ni++)
#pragma unroll
            for (int e = 0; e < 4; e++) acc[mi][ni][e] = 0.f;

    float4 va[2], vb[2];

    auto ldg = [&](int kb) {
#pragma unroll
        for (int j = 0; j < 2; j++) {
            int r = rr + 64 * j;
            va[j] = *reinterpret_cast<const float4*>(X  + (size_t)(m0 + r) * ND + kb + c4 * 4);
            vb[j] = *reinterpret_cast<const float4*>(Wt + (size_t)(n0 + r) * ND + kb + c4 * 4);
        }
    };
    auto sts = [&](int buf) {
#pragma unroll
        for (int j = 0; j < 2; j++) {
            int r = rr + 64 * j;
            {
                int mblk = r >> 4, gg = r & 7, hi = (r >> 3) & 1;
                float* p = &sA[buf][((mblk * 4 + k8s) * 8 + gg) * 16 + hi + 2 * khis];
                p[((0 ^ k8s) & 3) * 4] = tf32r(va[j].x);
                p[((1 ^ k8s) & 3) * 4] = tf32r(va[j].y);
                p[((2 ^ k8s) & 3) * 4] = tf32r(va[j].z);
                p[((3 ^ k8s) & 3) * 4] = tf32r(va[j].w);
            }
            {
                int nblk = r >> 3, gg = r & 7;
                float* p = &sB[buf][((nblk * 4 + k8s) * 8 + gg) * 8 + khis];
                p[((0 ^ k8s) & 3) * 2] = tf32r(vb[j].x);
                p[((1 ^ k8s) & 3) * 2] = tf32r(vb[j].y);
                p[((2 ^ k8s) & 3) * 2] = tf32r(vb[j].z);
                p[((3 ^ k8s) & 3) * 2] = tf32r(vb[j].w);
            }
        }
    };

    ldg(0);
    sts(0);
    __syncthreads();

    for (int kb = 0, it = 0; kb < ND; kb += 32, it++) {
        const int buf = it & 1;
        const bool more = (kb + 32) < ND;
        if (more) ldg(kb + 32);
#pragma unroll
        for (int ks = 0; ks < 4; ks++) {
            const int slot = (tg ^ ks) & 3;
            float4 af[2];
            af[0] = *reinterpret_cast<const float4*>(
                &sA[buf][(((wm2 + 0) * 4 + ks) * 8 + g) * 16 + slot * 4]);
            af[1] = *reinterpret_cast<const float4*>(
                &sA[buf][(((wm2 + 1) * 4 + ks) * 8 + g) * 16 + slot * 4]);
            float2 bf[4];
#pragma unroll
            for (int ni = 0; ni < 4; ni++)
                bf[ni] = *reinterpret_cast<const float2*>(
                    &sB[buf][(((wn4 + ni) * 4 + ks) * 8 + g) * 8 + slot * 2]);
#pragma unroll
            for (int mi = 0; mi < 2; mi++)
#pragma unroll
                for (int ni = 0; ni < 4; ni++)
                    mma8(acc[mi][ni], reinterpret_cast<const uint32_t*>(&af[mi]),
                         __float_as_uint(bf[ni].x), __float_as_uint(bf[ni].y));
        }
        if (more) sts(buf ^ 1);
        __syncthreads();
    }

#pragma unroll
    for (int mi = 0; mi < 2; mi++) {
#pragma unroll
        for (int ni = 0; ni < 4; ni++) {
            int row = m0 + (wm2 + mi) * 16 + g;
            int col = n0 + (wn4 + ni) * 8 + 2 * tg;
            float b0 = bias[col], b1 = bias[col + 1];
            *reinterpret_cast<float2*>(out + (size_t)row * ND + col) =
                make_float2(acc[mi][ni][0] + b0, acc[mi][ni][1] + b1);
            *reinterpret_cast<float2*>(out + (size_t)(row + 8) * ND + col) =
                make_float2(acc[mi][ni][2] + b0, acc[mi][ni][3] + b1);
        }
    }
}

// ---------------- kernel 3: attention ----------------------------------------
// smem layout (floats):
#define SQ_OFF  0        // [mblk8][k8_8][g8][slot4][v4]      = 8192
#define SKF_OFF 8192     // K half frag [nblk8][k8_8][g8][slot4][khi2] = 4096
#define SVF_OFF 12288    // V half frag, same shape           = 4096
#define SW_OFF  16384    // weights half, row-major 128 x 68  = 8704
#define SKM_OFF 25088    // key mask for tile                 = 128
#define ATTN_FLOATS 25216
#define ATTN_SMEM (ATTN_FLOATS * (int)sizeof(float))
#define SWS 68

__device__ __forceinline__ void stage_K_half(float* dst, const float* src, int tid) {
#pragma unroll
    for (int jj = 0; jj < 4; jj++) {
        int idx = tid + 256 * jj;
        int r = idx >> 4, c4 = idx & 15;
        float4 v = *reinterpret_cast<const float4*>(src + (size_t)r * ND + c4 * 4);
        int nblk = r >> 3, gk = r & 7, k8 = c4 >> 1, khi = c4 & 1;
        float* p = &dst[((nblk * 8 + k8) * 8 + gk) * 8 + khi];
        p[((0 ^ k8) & 3) * 2] = tf32r(v.x);
        p[((1 ^ k8) & 3) * 2] = tf32r(v.y);
        p[((2 ^ k8) & 3) * 2] = tf32r(v.z);
        p[((3 ^ k8) & 3) * 2] = tf32r(v.w);
    }
}

__device__ __forceinline__ void stage_V_half(float* dst, const float* src, int tid) {
#pragma unroll
    for (int jj = 0; jj < 4; jj++) {
        int idx = tid + 256 * jj;
        int r = idx >> 4, c4 = idx & 15;   // r = kv row (k dim), c4 = dh float4
        float4 v = *reinterpret_cast<const float4*>(src + (size_t)r * ND + c4 * 4);
        int nblk = c4 >> 1, k8 = r >> 3, tg = r & 3, khi = (r >> 2) & 1;
        int slot = ((tg ^ k8) & 3) * 2 + khi;
        int gb = (c4 & 1) * 4;
        float* p = &dst[((nblk * 8 + k8) * 8 + gb) * 8 + slot];
        p[0 * 8] = tf32r(v.x);
        p[1 * 8] = tf32r(v.y);
        p[2 * 8] = tf32r(v.z);
        p[3 * 8] = tf32r(v.w);
    }
}

__device__ __forceinline__ void smma_half(const float* sQ, const float* kbuf,
                                          int wid, int g, int tg, float (&acc)[8][4]) {
#pragma unroll
    for (int ni = 0; ni < 8; ni++)
#pragma unroll
        for (int e = 0; e < 4; e++) acc[ni][e] = 0.f;
#pragma unroll
    for (int ks = 0; ks < 8; ks++) {
        const int slot = (tg ^ ks) & 3;
        float4 a = *reinterpret_cast<const float4*>(
            &sQ[((wid * 8 + ks) * 8 + g) * 16 + slot * 4]);
#pragma unroll
        for (int ni = 0; ni < 8; ni++) {
            float2 bv = *reinterpret_cast<const float2*>(
                &kbuf[((ni * 8 + ks) * 8 + g) * 8 + slot * 2]);
            mma8(acc[ni], reinterpret_cast<const uint32_t*>(&a),
                 __float_as_uint(bv.x), __float_as_uint(bv.y));
        }
    }
}

// scale + masks, converting scores into base-2 logit space (t = S/8 * log2 e)
__device__ __forceinline__ void mask_half(float (&acc)[8][4], const float* sKMh,
                                          int col0, int causal, int rowg0, int rowg1, int tg) {
#pragma unroll
    for (int ni = 0; ni < 8; ni++)
#pragma unroll
        for (int e = 0; e < 4; e++) {
            int r = e >> 1, c = e & 1;
            int cl = ni * 8 + 2 * tg + c;
            float t = acc[ni][e] * CSCALE;
            if (sKMh[cl] == 0.f) t = -CUDART_INF_F;
            if (causal && (col0 + cl) > (r ? rowg1 : rowg0)) t = -CUDART_INF_F;
            acc[ni][e] = t;
        }
}

__global__ __launch_bounds__(256, 2) void attn_kernel(
    const int* __restrict__ causality, float* __restrict__ outp, float* __restrict__ attnp) {
    extern __shared__ float sh[];
    float* sQ  = sh + SQ_OFF;
    float* sKf = sh + SKF_OFF;
    float* sVf = sh + SVF_OFF;
    float* sW  = sh + SW_OFF;
    float* sKM = sh + SKM_OFF;

    const int qt = blockIdx.x, h = blockIdx.y, b = blockIdx.z;
    const int tid = threadIdx.x, wid = tid >> 5, lane = tid & 31;
    const int g = lane >> 2, tg = lane & 3;
    const int causal = *causality;
    const int q0 = qt * 128;

    // ---- stage Q (frag-major, tf32-rounded) ----
    {
        const float* qsrc = g_Q + ((size_t)(b * NL + q0) * ND + h * NDH);
#pragma unroll
        for (int jj = 0; jj < 8; jj++) {
            int idx = tid + 256 * jj;
            int r = idx >> 4, c4 = idx & 15;
            float4 v = *reinterpret_cast<const float4*>(qsrc + (size_t)r * ND + c4 * 4);
            int mblk = r >> 4, gg = r & 7, hi = (r >> 3) & 1, k8 = c4 >> 1, khi = c4 & 1;
            float* p = &sQ[((mblk * 8 + k8) * 8 + gg) * 16 + hi + 2 * khi];
            p[((0 ^ k8) & 3) * 4] = tf32r(v.x);
            p[((1 ^ k8) & 3) * 4] = tf32r(v.y);
            p[((2 ^ k8) & 3) * 4] = tf32r(v.z);
            p[((3 ^ k8) & 3) * 4] = tf32r(v.w);
        }
    }

    const int rowl0 = wid * 16 + g, rowl1 = rowl0 + 8;
    const int rowg0 = q0 + rowl0, rowg1 = q0 + rowl1;
    const float qm0 = g_qm[b * NL + rowg0];
    const float qm1 = g_qm[b * NL + rowg1];

    float mrun[2] = {-CUDART_INF_F, -CUDART_INF_F};
    float lrun[2] = {0.f, 0.f};
    const int ktmax = causal ? qt : 3;
    float acc[8][4];

    // ---- PASS A: softmax statistics (both K halves staged per tile) ----
    for (int kt = 0; kt <= ktmax; kt++) {
        const float* kbase = g_K + ((size_t)(b * NL + kt * 128) * ND + h * NDH);
        stage_K_half(sKf, kbase, tid);
        stage_K_half(sVf, kbase + (size_t)64 * ND, tid);
        if (tid < 128) sKM[tid] = g_km[b * NL + kt * 128 + tid];
        __syncthreads();

#pragma unroll
        for (int half = 0; half < 2; half++) {
            smma_half(sQ, half ? sVf : sKf, wid, g, tg, acc);
            mask_half(acc, sKM + half * 64, kt * 128 + half * 64, causal, rowg0, rowg1, tg);
#pragma unroll
            for (int r = 0; r < 2; r++) {
                float mx = -CUDART_INF_F;
#pragma unroll
                for (int ni = 0; ni < 8; ni++) {
                    mx = fmaxf(mx, acc[ni][2 * r]);
                    mx = fmaxf(mx, acc[ni][2 * r + 1]);
                }
                mx = fmaxf(mx, __shfl_xor_sync(0xffffffffu, mx, 1));
                mx = fmaxf(mx, __shfl_xor_sync(0xffffffffu, mx, 2));
                float mn = fmaxf(mrun[r], mx);
                if (mn != -CUDART_INF_F) {
                    float ps = 0.f;
#pragma unroll
                    for (int ni = 0; ni < 8; ni++) {
                        ps += ex2(acc[ni][2 * r] - mn);
                        ps += ex2(acc[ni][2 * r + 1] - mn);
                    }
                    ps += __shfl_xor_sync(0xffffffffu, ps, 1);
                    ps += __shfl_xor_sync(0xffffffffu, ps, 2);
                    lrun[r] = lrun[r] * ex2(mrun[r] - mn) + ps;
                    mrun[r] = mn;
                }
            }
        }
        __syncthreads();
    }

    float muse[2], invl[2];
    muse[0] = lrun[0] > 0.f ? mrun[0] : 0.f;
    invl[0] = lrun[0] > 0.f ? qm0 / lrun[0] : 0.f;
    muse[1] = lrun[1] > 0.f ? mrun[1] : 0.f;
    invl[1] = lrun[1] > 0.f ? qm1 / lrun[1] : 0.f;

    float oacc[8][4];
#pragma unroll
    for (int ni = 0; ni < 8; ni++)
#pragma unroll
        for (int e = 0; e < 4; e++) oacc[ni][e] = 0.f;

    // ---- PASS B: weights out + O accumulation, 64-col halves ----
    for (int kt = 0; kt < 4; kt++) {
        if (causal && kt > qt) {
            if (attnp) {
                float4 z = make_float4(0.f, 0.f, 0.f, 0.f);
#pragma unroll
                for (int jj = 0; jj < 16; jj++) {
                    int idx = tid + 256 * jj;
                    int row = idx >> 5, c4 = idx & 31;
                    *reinterpret_cast<float4*>(
                        attnp + ((size_t)(b * NH + h) * NL + q0 + row) * NL + kt * 128 + c4 * 4) = z;
                }
            }
            continue;
        }
        const float* kbase = g_K + ((size_t)(b * NL + kt * 128) * ND + h * NDH);
        const float* vbase = g_V + ((size_t)(b * NL + kt * 128) * ND + h * NDH);

#pragma unroll
        for (int half = 0; half < 2; half++) {
            stage_K_half(sKf, kbase + (size_t)(half * 64) * ND, tid);
            stage_V_half(sVf, vbase + (size_t)(half * 64) * ND, tid);
            if (half == 0 && tid < 128) sKM[tid] = g_km[b * NL + kt * 128 + tid];
            __syncthreads();

            smma_half(sQ, sKf, wid, g, tg, acc);
            mask_half(acc, sKM + half * 64, kt * 128 + half * 64, causal, rowg0, rowg1, tg);

            // normalized weights -> sW (row-major half tile)
#pragma unroll
            for (int ni = 0; ni < 8; ni++) {
                float w00 = ex2(acc[ni][0] - muse[0]) * invl[0];
                float w01 = ex2(acc[ni][1] - muse[0]) * invl[0];
                float w10 = ex2(acc[ni][2] - muse[1]) * invl[1];
                float w11 = ex2(acc[ni][3] - muse[1]) * invl[1];
                *reinterpret_cast<float2*>(&sW[rowl0 * SWS + ni * 8 + 2 * tg]) = make_float2(w00, w01);
                *reinterpret_cast<float2*>(&sW[rowl1 * SWS + ni * 8 + 2 * tg]) = make_float2(w10, w11);
            }
            __syncwarp();

            if (attnp) {
#pragma unroll
                for (int j = 0; j < 8; j++) {
                    int fidx = lane + 32 * j;
                    int rl = fidx >> 4, c4 = fidx & 15;
                    int row = wid * 16 + rl;
                    float4 v = *reinterpret_cast<const float4*>(&sW[row * SWS + c4 * 4]);
                    *reinterpret_cast<float4*>(
                        attnp + ((size_t)(b * NH + h) * NL + q0 + row) * NL +
                        kt * 128 + half * 64 + c4 * 4) = v;
                }
            }

            // O += W_half * V_half
            const float* wr0 = sW + (size_t)rowl0 * SWS;
            const float* wr1 = sW + (size_t)rowl1 * SWS;
#pragma unroll
            for (int ks = 0; ks < 8; ks++) {
                const int slot = (tg ^ ks) & 3;
                uint32_t a[4];
                a[0] = tf32u(wr0[ks * 8 + tg]);
                a[1] = tf32u(wr1[ks * 8 + tg]);
                a[2] = tf32u(wr0[ks * 8 + tg + 4]);
                a[3] = tf32u(wr1[ks * 8 + tg + 4]);
#pragma unroll
                for (int ni = 0; ni < 8; ni++) {
                    float2 bv = *reinterpret_cast<const float2*>(
                        &sVf[((ni * 8 + ks) * 8 + g) * 8 + slot * 2]);
                    mma8(oacc[ni], a, __float_as_uint(bv.x), __float_as_uint(bv.y));
                }
            }
            __syncthreads();
        }
    }

    // epilogue: out[b][q][h*64 + d]
#pragma unroll
    for (int ni = 0; ni < 8; ni++) {
        int col = h * NDH + ni * 8 + 2 * tg;
        *reinterpret_cast<float2*>(outp + ((size_t)b * NL + rowg0) * ND + col) =
            make_float2(oacc[ni][0], oacc[ni][1]);
        *reinterpret_cast<float2*>(outp + ((size_t)b * NL + rowg1) * ND + col) =
            make_float2(oacc[ni][2], oacc[ni][3]);
    }
}

// ---------------- launcher ----------------------------------------------------
extern "C" void kernel_launch(void* const* d_in, const int* in_sizes, int n_in,
                              void* d_out, int out_size) {
    (void)in_sizes; (void)n_in;
    const float* queries = (const float*)d_in[0];
    const float* keys    = (const float*)d_in[1];
    const float* Wq = (const float*)d_in[2];
    const float* bq = (const float*)d_in[3];
    const float* Wk = (const float*)d_in[4];
    const float* bk = (const float*)d_in[5];
    const float* Wv = (const float*)d_in[6];
    const float* bv = (const float*)d_in[7];
    const int* caus = (const int*)d_in[8];

    float* outp = (float*)d_out;
    const size_t o_elems = (size_t)NB * NL * ND;
    const size_t a_elems = (size_t)NB * NH * NL * NL;
    float* attnp = ((size_t)out_size >= o_elems + a_elems) ? (outp + o_elems) : nullptr;

    cudaFuncSetAttribute(attn_kernel, cudaFuncAttributeMaxDynamicSharedMemorySize, ATTN_SMEM);

    mask_kernel<<<MTOT / 4, 128>>>(queries, keys);
    proj_kernel<<<dim3(4, 128, 3), 512>>>(queries, keys, Wq, bq, Wk, bk, Wv, bv);
    attn_kernel<<<dim3(4, NH, NB), 256, ATTN_SMEM>>>(caus, outp, attnp);
}